// round 1
// baseline (speedup 1.0000x reference)
#include <cuda_runtime.h>
#include <math.h>

#define BB 4
#define CC 64
#define HH 96
#define WW 96
#define NN (HH*WW)      // 9216
#define HP (HH/2)
#define WP (WW/2)
#define MM (HP*WP)      // 2304
#define KK 64

// Scratch (no allocations allowed): ~14.2 MB total
__device__ float g_q [BB*KK*NN];   // q at full res, [b][k][n]
__device__ float g_k [BB*KK*MM];   // k at pooled res, [b][k][m]
__device__ float g_v [BB*CC*MM];   // pooled x, [b][c][m]
__device__ float g_ea[BB*MM];      // sigmoid edge gate, [b][m]

// ---------------------------------------------------------------------------
// P1: maxpool(x), maxpool(c2), k = Wq*xp + bq, v = xp, edge-attention gate ea
// One block = 32 pooled pixels of one batch. 256 threads.
// ---------------------------------------------------------------------------
__global__ void __launch_bounds__(256) prep_kernel(
    const float* __restrict__ c2, const float* __restrict__ x,
    const float* __restrict__ w_ea1, const float* __restrict__ bn_w,
    const float* __restrict__ bn_b,  const float* __restrict__ bn_m,
    const float* __restrict__ bn_v,  const float* __restrict__ w_ea2,
    const float* __restrict__ b_ea2, const float* __restrict__ w_q,
    const float* __restrict__ b_q)
{
    extern __shared__ float sm[];
    float* sWq  = sm;                 // [64][65]
    float* sW1  = sWq  + 64*65;       // [64][129]
    float* sXp  = sW1  + 64*129;      // [32][65]
    float* sC2p = sXp  + 32*65;       // [32][65]
    float* sH   = sC2p + 32*65;       // [32][65]

    const int b   = blockIdx.y;
    const int m0  = blockIdx.x * 32;
    const int tid = threadIdx.x;

    for (int i = tid; i < 64*64;  i += 256) sWq[(i>>6)*65  + (i&63)]  = w_q[i];
    for (int i = tid; i < 64*128; i += 256) sW1[(i>>7)*129 + (i&127)] = w_ea1[i];

    // pooling (2x2 max)
    for (int job = tid; job < 2048; job += 256) {
        int c = job >> 5, p = job & 31;
        int m = m0 + p;
        int py = m / WP, px = m % WP;
        int base = ((b*CC + c)*HH + 2*py)*WW + 2*px;
        float vx = fmaxf(fmaxf(x[base],  x[base+1]),  fmaxf(x[base+WW],  x[base+WW+1]));
        float vc = fmaxf(fmaxf(c2[base], c2[base+1]), fmaxf(c2[base+WW], c2[base+WW+1]));
        sXp [p*65 + c] = vx;
        sC2p[p*65 + c] = vc;
        g_v[(b*CC + c)*MM + m] = vx;
    }
    __syncthreads();

    // k conv (Wq · xp + bq) and edge hidden h = ReLU(BN(Wea1 · [c2p;xp]))
    for (int job = tid; job < 2048; job += 256) {
        int o = job >> 5, p = job & 31;
        const float* wr = sWq + o*65;
        const float* xr = sXp + p*65;
        const float* cr = sC2p + p*65;
        float acc = b_q[o];
        #pragma unroll 16
        for (int c = 0; c < 64; c++) acc += wr[c]*xr[c];
        g_k[(b*KK + o)*MM + m0 + p] = acc;

        const float* w1 = sW1 + o*129;
        float h = 0.f;
        #pragma unroll 16
        for (int c = 0; c < 64; c++) h += w1[c]*cr[c];
        #pragma unroll 16
        for (int c = 0; c < 64; c++) h += w1[64+c]*xr[c];
        float scale = bn_w[o] * rsqrtf(bn_v[o] + 1e-5f);
        h = (h - bn_m[o]) * scale + bn_b[o];
        sH[p*65 + o] = fmaxf(h, 0.f);
    }
    __syncthreads();

    if (tid < 32) {
        int p = tid;
        const float* hr = sH + p*65;
        float acc = b_ea2[0];
        #pragma unroll 16
        for (int o = 0; o < 64; o++) acc += w_ea2[o]*hr[o];
        g_ea[b*MM + m0 + p] = 1.f / (1.f + __expf(-acc));
    }
}

// ---------------------------------------------------------------------------
// P2: q = Wq * x + bq at full resolution. One block = 64 pixels.
// ---------------------------------------------------------------------------
__global__ void __launch_bounds__(256) q_kernel(
    const float* __restrict__ x, const float* __restrict__ w_q,
    const float* __restrict__ b_q)
{
    __shared__ float sX [64*65];
    __shared__ float sWq[64*65];
    const int b   = blockIdx.y;
    const int n0  = blockIdx.x * 64;
    const int tid = threadIdx.x;

    for (int i = tid; i < 64*64; i += 256) sWq[(i>>6)*65 + (i&63)] = w_q[i];
    for (int i = tid; i < 64*64; i += 256) {
        int c = i >> 6, p = i & 63;
        sX[p*65 + c] = x[(b*CC + c)*NN + n0 + p];
    }
    __syncthreads();
    for (int job = tid; job < 4096; job += 256) {
        int o = job >> 6, p = job & 63;
        const float* wr = sWq + o*65;
        const float* xr = sX  + p*65;
        float acc = b_q[o];
        #pragma unroll 16
        for (int c = 0; c < 64; c++) acc += wr[c]*xr[c];
        g_q[(b*KK + o)*NN + n0 + p] = acc;
    }
}

// ---------------------------------------------------------------------------
// A: fused flash attention. Block = 64 query rows; stream 36 key tiles of 64.
// 256 threads as 16x16; each thread owns a 4x4 tile of S and of O.
// Epilogue: out = gamma * (O / l) + x
// ---------------------------------------------------------------------------
__global__ void __launch_bounds__(256) attn_kernel(
    const float* __restrict__ x, const float* __restrict__ gamma,
    float* __restrict__ out)
{
    extern __shared__ float sm[];
    float* Qs  = sm;             // [d][r]  64*64
    float* Ks  = Qs + 4096;      // [d][j]  64*64
    float* Vs  = Ks + 4096;      // [j][c]  64*68 (padded)
    float* Ps  = Vs + 64*68;     // [j][r]  64*68 (padded)
    float* sEa = Ps + 64*68;     // [64]

    const int b   = blockIdx.y;
    const int n0  = blockIdx.x * 64;
    const int tid = threadIdx.x;
    const int ty  = tid >> 4, tx = tid & 15;
    const int ty4 = ty * 4,  tx4 = tx * 4;

    for (int i = tid; i < 4096; i += 256) {
        int d = i >> 6, r = i & 63;
        Qs[d*64 + r] = g_q[(b*KK + d)*NN + n0 + r];
    }

    float mrow[4], lrow[4], O[4][4];
    #pragma unroll
    for (int i = 0; i < 4; i++) {
        mrow[i] = -1e30f; lrow[i] = 0.f;
        #pragma unroll
        for (int j = 0; j < 4; j++) O[i][j] = 0.f;
    }

    for (int t = 0; t < MM/64; t++) {
        const int mb = t * 64;
        __syncthreads();   // guard Ks/Vs/Ps reuse from previous iteration
        for (int i = tid; i < 4096; i += 256) {
            int d = i >> 6, j = i & 63;
            Ks[d*64 + j] = g_k[(b*KK + d)*MM + mb + j];
        }
        for (int i = tid; i < 4096; i += 256) {
            int c = i >> 6, j = i & 63;
            Vs[j*68 + c] = g_v[(b*CC + c)*MM + mb + j];
        }
        if (tid < 64) sEa[tid] = g_ea[b*MM + mb + tid];
        __syncthreads();

        // S = Q^T K   (s[i][j] = S[n0+ty4+i][mb+tx4+j])
        float s[4][4];
        #pragma unroll
        for (int i = 0; i < 4; i++)
            #pragma unroll
            for (int j = 0; j < 4; j++) s[i][j] = 0.f;

        #pragma unroll 8
        for (int d = 0; d < 64; d++) {
            float4 a = *(const float4*)(Qs + d*64 + ty4);
            float4 k = *(const float4*)(Ks + d*64 + tx4);
            s[0][0] += a.x*k.x; s[0][1] += a.x*k.y; s[0][2] += a.x*k.z; s[0][3] += a.x*k.w;
            s[1][0] += a.y*k.x; s[1][1] += a.y*k.y; s[1][2] += a.y*k.z; s[1][3] += a.y*k.w;
            s[2][0] += a.z*k.x; s[2][1] += a.z*k.y; s[2][2] += a.z*k.z; s[2][3] += a.z*k.w;
            s[3][0] += a.w*k.x; s[3][1] += a.w*k.y; s[3][2] += a.w*k.z; s[3][3] += a.w*k.w;
        }

        // scale by edge gate (per key column)
        float e0 = sEa[tx4], e1 = sEa[tx4+1], e2 = sEa[tx4+2], e3 = sEa[tx4+3];
        #pragma unroll
        for (int i = 0; i < 4; i++) {
            s[i][0] *= e0; s[i][1] *= e1; s[i][2] *= e2; s[i][3] *= e3;
        }

        // online softmax (row spread across the 16 tx lanes = low 4 lane bits)
        #pragma unroll
        for (int i = 0; i < 4; i++) {
            float rm = fmaxf(fmaxf(s[i][0], s[i][1]), fmaxf(s[i][2], s[i][3]));
            #pragma unroll
            for (int off = 8; off; off >>= 1)
                rm = fmaxf(rm, __shfl_xor_sync(0xffffffffu, rm, off));
            float mn = fmaxf(mrow[i], rm);
            float alpha = __expf(mrow[i] - mn);
            float rs = 0.f;
            #pragma unroll
            for (int j = 0; j < 4; j++) { s[i][j] = __expf(s[i][j] - mn); rs += s[i][j]; }
            #pragma unroll
            for (int off = 8; off; off >>= 1)
                rs += __shfl_xor_sync(0xffffffffu, rs, off);
            lrow[i] = lrow[i]*alpha + rs;
            mrow[i] = mn;
            #pragma unroll
            for (int j = 0; j < 4; j++) O[i][j] *= alpha;
        }

        // stash P transposed for the PV GEMM
        #pragma unroll
        for (int i = 0; i < 4; i++)
            #pragma unroll
            for (int jj = 0; jj < 4; jj++)
                Ps[(tx4+jj)*68 + ty4 + i] = s[i][jj];
        __syncthreads();

        // O += P V^T   (O[i][jc] = out[row ty4+i][chan tx4+jc])
        #pragma unroll 8
        for (int j = 0; j < 64; j++) {
            float4 p = *(const float4*)(Ps + j*68 + ty4);
            float4 v = *(const float4*)(Vs + j*68 + tx4);
            O[0][0] += p.x*v.x; O[0][1] += p.x*v.y; O[0][2] += p.x*v.z; O[0][3] += p.x*v.w;
            O[1][0] += p.y*v.x; O[1][1] += p.y*v.y; O[1][2] += p.y*v.z; O[1][3] += p.y*v.w;
            O[2][0] += p.z*v.x; O[2][1] += p.z*v.y; O[2][2] += p.z*v.z; O[2][3] += p.z*v.w;
            O[3][0] += p.w*v.x; O[3][1] += p.w*v.y; O[3][2] += p.w*v.z; O[3][3] += p.w*v.w;
        }
    }

    // finalize: divide by softmax denom
    #pragma unroll
    for (int i = 0; i < 4; i++) {
        float inv = 1.f / lrow[i];
        #pragma unroll
        for (int j = 0; j < 4; j++) O[i][j] *= inv;
    }

    const float g = gamma[0];
    __syncthreads();
    // stage O through smem (reuse Vs) for coalesced output writes
    #pragma unroll
    for (int i = 0; i < 4; i++)
        #pragma unroll
        for (int j = 0; j < 4; j++)
            Vs[(tx4+j)*68 + ty4 + i] = O[i][j];
    __syncthreads();
    for (int idx = tid; idx < 4096; idx += 256) {
        int c = idx >> 6, r = idx & 63;
        int gi = (b*CC + c)*NN + n0 + r;
        out[gi] = g * Vs[c*68 + r] + x[gi];
    }
}

// ---------------------------------------------------------------------------
extern "C" void kernel_launch(void* const* d_in, const int* in_sizes, int n_in,
                              void* d_out, int out_size)
{
    const float* c2    = (const float*)d_in[0];
    const float* x     = (const float*)d_in[1];
    const float* w_ea1 = (const float*)d_in[2];
    const float* bn_w  = (const float*)d_in[3];
    const float* bn_b  = (const float*)d_in[4];
    const float* bn_m  = (const float*)d_in[5];
    const float* bn_v  = (const float*)d_in[6];
    const float* w_ea2 = (const float*)d_in[7];
    const float* b_ea2 = (const float*)d_in[8];
    const float* w_q   = (const float*)d_in[9];
    const float* b_q   = (const float*)d_in[10];
    const float* gamma = (const float*)d_in[11];
    float* out = (float*)d_out;

    const int P1_SMEM   = (64*65 + 64*129 + 3*32*65) * (int)sizeof(float);   // 74624 B
    const int ATTN_SMEM = (4096 + 4096 + 2*64*68 + 64) * (int)sizeof(float); // 67840 B

    cudaFuncSetAttribute(prep_kernel, cudaFuncAttributeMaxDynamicSharedMemorySize, P1_SMEM);
    cudaFuncSetAttribute(attn_kernel, cudaFuncAttributeMaxDynamicSharedMemorySize, ATTN_SMEM);

    prep_kernel<<<dim3(MM/32, BB), 256, P1_SMEM>>>(c2, x, w_ea1, bn_w, bn_b, bn_m,
                                                   bn_v, w_ea2, b_ea2, w_q, b_q);
    q_kernel<<<dim3(NN/64, BB), 256>>>(x, w_q, b_q);
    attn_kernel<<<dim3(NN/64, BB), 256, ATTN_SMEM>>>(x, gamma, out);
}

// round 2
// speedup vs baseline: 1.1258x; 1.1258x over previous
#include <cuda_runtime.h>
#include <math.h>

#define BB 4
#define CC 64
#define HH 96
#define WW 96
#define NN (HH*WW)      // 9216
#define HP (HH/2)
#define WP (WW/2)
#define MM (HP*WP)      // 2304
#define KK 64

typedef unsigned long long u64;

// Scratch (no allocations allowed): ~14.2 MB total
__device__ float g_q [BB*KK*NN];   // q at full res, [b][k][n]
__device__ float g_k [BB*KK*MM];   // k at pooled res, [b][k][m]
__device__ float g_v [BB*CC*MM];   // pooled x, [b][c][m]
__device__ float g_ea[BB*MM];      // sigmoid edge gate, [b][m]

// ---- packed f32x2 helpers (ptxas will not auto-fuse; PTX-only path) -------
__device__ __forceinline__ u64 pack2(float v) {
    u64 r; asm("mov.b64 %0, {%1,%1};" : "=l"(r) : "f"(v)); return r;
}
__device__ __forceinline__ u64 fma2(u64 a, u64 b, u64 c) {
    u64 d; asm("fma.rn.f32x2 %0, %1, %2, %3;" : "=l"(d) : "l"(a), "l"(b), "l"(c)); return d;
}
__device__ __forceinline__ u64 mul2(u64 a, u64 b) {
    u64 d; asm("mul.rn.f32x2 %0, %1, %2;" : "=l"(d) : "l"(a), "l"(b)); return d;
}
__device__ __forceinline__ void unpk(u64 v, float& lo, float& hi) {
    asm("mov.b64 {%0,%1}, %2;" : "=f"(lo), "=f"(hi) : "l"(v));
}

// ---------------------------------------------------------------------------
// P1: maxpool(x), maxpool(c2), k = Wq*xp + bq, v = xp, edge-attention gate ea
// ---------------------------------------------------------------------------
__global__ void __launch_bounds__(256) prep_kernel(
    const float* __restrict__ c2, const float* __restrict__ x,
    const float* __restrict__ w_ea1, const float* __restrict__ bn_w,
    const float* __restrict__ bn_b,  const float* __restrict__ bn_m,
    const float* __restrict__ bn_v,  const float* __restrict__ w_ea2,
    const float* __restrict__ b_ea2, const float* __restrict__ w_q,
    const float* __restrict__ b_q)
{
    extern __shared__ float sm[];
    float* sWq  = sm;                 // [64][65]
    float* sW1  = sWq  + 64*65;       // [64][129]
    float* sXp  = sW1  + 64*129;      // [32][65]
    float* sC2p = sXp  + 32*65;       // [32][65]
    float* sH   = sC2p + 32*65;       // [32][65]

    const int b   = blockIdx.y;
    const int m0  = blockIdx.x * 32;
    const int tid = threadIdx.x;

    for (int i = tid; i < 64*64;  i += 256) sWq[(i>>6)*65  + (i&63)]  = w_q[i];
    for (int i = tid; i < 64*128; i += 256) sW1[(i>>7)*129 + (i&127)] = w_ea1[i];

    for (int job = tid; job < 2048; job += 256) {
        int c = job >> 5, p = job & 31;
        int m = m0 + p;
        int py = m / WP, px = m % WP;
        int base = ((b*CC + c)*HH + 2*py)*WW + 2*px;
        float vx = fmaxf(fmaxf(x[base],  x[base+1]),  fmaxf(x[base+WW],  x[base+WW+1]));
        float vc = fmaxf(fmaxf(c2[base], c2[base+1]), fmaxf(c2[base+WW], c2[base+WW+1]));
        sXp [p*65 + c] = vx;
        sC2p[p*65 + c] = vc;
        g_v[(b*CC + c)*MM + m] = vx;
    }
    __syncthreads();

    for (int job = tid; job < 2048; job += 256) {
        int o = job >> 5, p = job & 31;
        const float* wr = sWq + o*65;
        const float* xr = sXp + p*65;
        const float* cr = sC2p + p*65;
        float acc = b_q[o];
        #pragma unroll 16
        for (int c = 0; c < 64; c++) acc += wr[c]*xr[c];
        g_k[(b*KK + o)*MM + m0 + p] = acc;

        const float* w1 = sW1 + o*129;
        float h = 0.f;
        #pragma unroll 16
        for (int c = 0; c < 64; c++) h += w1[c]*cr[c];
        #pragma unroll 16
        for (int c = 0; c < 64; c++) h += w1[64+c]*xr[c];
        float scale = bn_w[o] * rsqrtf(bn_v[o] + 1e-5f);
        h = (h - bn_m[o]) * scale + bn_b[o];
        sH[p*65 + o] = fmaxf(h, 0.f);
    }
    __syncthreads();

    if (tid < 32) {
        int p = tid;
        const float* hr = sH + p*65;
        float acc = b_ea2[0];
        #pragma unroll 16
        for (int o = 0; o < 64; o++) acc += w_ea2[o]*hr[o];
        g_ea[b*MM + m0 + p] = 1.f / (1.f + __expf(-acc));
    }
}

// ---------------------------------------------------------------------------
// P2: q = Wq * x + bq at full resolution
// ---------------------------------------------------------------------------
__global__ void __launch_bounds__(256) q_kernel(
    const float* __restrict__ x, const float* __restrict__ w_q,
    const float* __restrict__ b_q)
{
    __shared__ float sX [64*65];
    __shared__ float sWq[64*65];
    const int b   = blockIdx.y;
    const int n0  = blockIdx.x * 64;
    const int tid = threadIdx.x;

    for (int i = tid; i < 64*64; i += 256) sWq[(i>>6)*65 + (i&63)] = w_q[i];
    for (int i = tid; i < 64*64; i += 256) {
        int c = i >> 6, p = i & 63;
        sX[p*65 + c] = x[(b*CC + c)*NN + n0 + p];
    }
    __syncthreads();
    for (int job = tid; job < 4096; job += 256) {
        int o = job >> 6, p = job & 63;
        const float* wr = sWq + o*65;
        const float* xr = sX  + p*65;
        float acc = b_q[o];
        #pragma unroll 16
        for (int c = 0; c < 64; c++) acc += wr[c]*xr[c];
        g_q[(b*KK + o)*NN + n0 + p] = acc;
    }
}

// ---------------------------------------------------------------------------
// A: fused flash attention, f32x2 packed math.
// Block = 64 query rows, 256 threads as 16x16, 4x4 microtile/thread.
// Smem: Qs | KP (Ks during QK, Ps during PV, O-staging at end) | Vs | ea
//   -> 50.3 KB => 4 blocks/SM => 576 blocks in a single wave (148*4=592).
// ---------------------------------------------------------------------------
__global__ void __launch_bounds__(256, 4) attn_kernel(
    const float* __restrict__ x, const float* __restrict__ gamma,
    float* __restrict__ out)
{
    extern __shared__ float sm[];
    float* Qs  = sm;             // [d][r]  64*64
    float* KP  = Qs + 4096;      // [d][j] stride 68 (Ks), later [j][r] (Ps)
    float* Vs  = KP + 64*68;     // [j][c] stride 68
    float* sEa = Vs + 64*68;     // [64]

    const int b   = blockIdx.y;
    const int n0  = blockIdx.x * 64;
    const int tid = threadIdx.x;
    const int ty  = tid >> 4, tx = tid & 15;
    const int ty4 = ty * 4,  tx4 = tx * 4;

    for (int i = tid; i < 4096; i += 256) {
        int d = i >> 6, r = i & 63;
        Qs[d*64 + r] = g_q[(b*KK + d)*NN + n0 + r];
    }

    float mrow[4], lrow[4];
    u64 O2[4][2];
    #pragma unroll
    for (int i = 0; i < 4; i++) {
        mrow[i] = -1e30f; lrow[i] = 0.f;
        O2[i][0] = 0ull; O2[i][1] = 0ull;
    }

    for (int t = 0; t < MM/64; t++) {
        const int mb = t * 64;
        __syncthreads();   // prev-tile PV reads of KP/Vs done before refill
        for (int i = tid; i < 4096; i += 256) {
            int d = i >> 6, j = i & 63;
            KP[d*68 + j] = g_k[(b*KK + d)*MM + mb + j];
        }
        for (int i = tid; i < 4096; i += 256) {
            int c = i >> 6, j = i & 63;
            Vs[j*68 + c] = g_v[(b*CC + c)*MM + mb + j];
        }
        if (tid < 64) sEa[tid] = g_ea[b*MM + mb + tid];
        __syncthreads();

        // ---- S = Q^T K (packed along j) --------------------------------
        u64 s2[4][2];
        #pragma unroll
        for (int i = 0; i < 4; i++) { s2[i][0] = 0ull; s2[i][1] = 0ull; }

        #pragma unroll 8
        for (int d = 0; d < 64; d++) {
            float4     a  = *(const float4*)    (Qs + d*64 + ty4);
            ulonglong2 kv = *(const ulonglong2*)(KP + d*68 + tx4);
            u64 a0 = pack2(a.x), a1 = pack2(a.y), a2 = pack2(a.z), a3 = pack2(a.w);
            s2[0][0] = fma2(a0, kv.x, s2[0][0]); s2[0][1] = fma2(a0, kv.y, s2[0][1]);
            s2[1][0] = fma2(a1, kv.x, s2[1][0]); s2[1][1] = fma2(a1, kv.y, s2[1][1]);
            s2[2][0] = fma2(a2, kv.x, s2[2][0]); s2[2][1] = fma2(a2, kv.y, s2[2][1]);
            s2[3][0] = fma2(a3, kv.x, s2[3][0]); s2[3][1] = fma2(a3, kv.y, s2[3][1]);
        }

        // ---- edge gate (packed per key column) -------------------------
        u64 ep0 = *(const u64*)(sEa + tx4);
        u64 ep1 = *(const u64*)(sEa + tx4 + 2);
        float s[4][4];
        #pragma unroll
        for (int i = 0; i < 4; i++) {
            s2[i][0] = mul2(s2[i][0], ep0);
            s2[i][1] = mul2(s2[i][1], ep1);
            unpk(s2[i][0], s[i][0], s[i][1]);
            unpk(s2[i][1], s[i][2], s[i][3]);
        }

        // ---- online softmax (row spread over 16 tx lanes) --------------
        #pragma unroll
        for (int i = 0; i < 4; i++) {
            float rm = fmaxf(fmaxf(s[i][0], s[i][1]), fmaxf(s[i][2], s[i][3]));
            #pragma unroll
            for (int off = 8; off; off >>= 1)
                rm = fmaxf(rm, __shfl_xor_sync(0xffffffffu, rm, off));
            float mn = fmaxf(mrow[i], rm);
            float alpha = __expf(mrow[i] - mn);
            float rs = 0.f;
            #pragma unroll
            for (int j = 0; j < 4; j++) { s[i][j] = __expf(s[i][j] - mn); rs += s[i][j]; }
            #pragma unroll
            for (int off = 8; off; off >>= 1)
                rs += __shfl_xor_sync(0xffffffffu, rs, off);
            lrow[i] = lrow[i]*alpha + rs;
            mrow[i] = mn;
            u64 al = pack2(alpha);
            O2[i][0] = mul2(O2[i][0], al);
            O2[i][1] = mul2(O2[i][1], al);
        }

        // ---- P -> smem transposed (KP region: Ks is dead now) ----------
        __syncthreads();   // all warps done reading Ks
        #pragma unroll
        for (int i = 0; i < 4; i++)
            #pragma unroll
            for (int jj = 0; jj < 4; jj++)
                KP[(tx4+jj)*68 + ty4 + i] = s[i][jj];
        __syncthreads();

        // ---- O += P V^T (packed along channel) -------------------------
        #pragma unroll 8
        for (int j = 0; j < 64; j++) {
            float4     p  = *(const float4*)    (KP + j*68 + ty4);
            ulonglong2 vv = *(const ulonglong2*)(Vs + j*68 + tx4);
            u64 p0 = pack2(p.x), p1 = pack2(p.y), p2 = pack2(p.z), p3 = pack2(p.w);
            O2[0][0] = fma2(p0, vv.x, O2[0][0]); O2[0][1] = fma2(p0, vv.y, O2[0][1]);
            O2[1][0] = fma2(p1, vv.x, O2[1][0]); O2[1][1] = fma2(p1, vv.y, O2[1][1]);
            O2[2][0] = fma2(p2, vv.x, O2[2][0]); O2[2][1] = fma2(p2, vv.y, O2[2][1]);
            O2[3][0] = fma2(p3, vv.x, O2[3][0]); O2[3][1] = fma2(p3, vv.y, O2[3][1]);
        }
    }

    // ---- finalize: O/l, stage via smem, out = gamma*O + x --------------
    float O[4][4];
    #pragma unroll
    for (int i = 0; i < 4; i++) {
        unpk(O2[i][0], O[i][0], O[i][1]);
        unpk(O2[i][1], O[i][2], O[i][3]);
        float inv = 1.f / lrow[i];
        #pragma unroll
        for (int j = 0; j < 4; j++) O[i][j] *= inv;
    }

    const float g = gamma[0];
    __syncthreads();
    #pragma unroll
    for (int i = 0; i < 4; i++)
        #pragma unroll
        for (int j = 0; j < 4; j++)
            KP[(tx4+j)*68 + ty4 + i] = O[i][j];
    __syncthreads();
    for (int idx = tid; idx < 4096; idx += 256) {
        int c = idx >> 6, r = idx & 63;
        int gi = (b*CC + c)*NN + n0 + r;
        out[gi] = g * KP[c*68 + r] + x[gi];
    }
}

// ---------------------------------------------------------------------------
extern "C" void kernel_launch(void* const* d_in, const int* in_sizes, int n_in,
                              void* d_out, int out_size)
{
    const float* c2    = (const float*)d_in[0];
    const float* x     = (const float*)d_in[1];
    const float* w_ea1 = (const float*)d_in[2];
    const float* bn_w  = (const float*)d_in[3];
    const float* bn_b  = (const float*)d_in[4];
    const float* bn_m  = (const float*)d_in[5];
    const float* bn_v  = (const float*)d_in[6];
    const float* w_ea2 = (const float*)d_in[7];
    const float* b_ea2 = (const float*)d_in[8];
    const float* w_q   = (const float*)d_in[9];
    const float* b_q   = (const float*)d_in[10];
    const float* gamma = (const float*)d_in[11];
    float* out = (float*)d_out;

    const int P1_SMEM   = (64*65 + 64*129 + 3*32*65) * (int)sizeof(float);   // 74624 B
    const int ATTN_SMEM = (4096 + 2*64*68 + 64) * (int)sizeof(float);        // 51456 B

    cudaFuncSetAttribute(prep_kernel, cudaFuncAttributeMaxDynamicSharedMemorySize, P1_SMEM);
    cudaFuncSetAttribute(attn_kernel, cudaFuncAttributeMaxDynamicSharedMemorySize, ATTN_SMEM);

    prep_kernel<<<dim3(MM/32, BB), 256, P1_SMEM>>>(c2, x, w_ea1, bn_w, bn_b, bn_m,
                                                   bn_v, w_ea2, b_ea2, w_q, b_q);
    q_kernel<<<dim3(NN/64, BB), 256>>>(x, w_q, b_q);
    attn_kernel<<<dim3(NN/64, BB), 256, ATTN_SMEM>>>(x, gamma, out);
}

// round 4
// speedup vs baseline: 2.0671x; 1.8361x over previous
#include <cuda_runtime.h>
#include <math.h>
#include <stdint.h>

#define BB 4
#define CC 64
#define HH 96
#define WW 96
#define NN (HH*WW)      // 9216
#define HP (HH/2)
#define WP (WW/2)
#define MM (HP*WP)      // 2304
#define KK 64

// Scratch (no allocations allowed)
__device__ float g_q [BB*KK*NN];   // q, [b][k][n]
__device__ float g_k [BB*KK*MM];   // k, [b][k][m]
__device__ float g_v [BB*CC*MM];   // pooled x, [b][c][m]
__device__ float g_ea[BB*MM];      // sigmoid edge gate, [b][m]

// ---- tf32 / mma helpers ---------------------------------------------------
__device__ __forceinline__ uint32_t to_tf32(float f) {
    uint32_t u; asm("cvt.rna.tf32.f32 %0, %1;" : "=r"(u) : "f"(f)); return u;
}
__device__ __forceinline__ float tf32f(float f) {
    return __uint_as_float(to_tf32(f));
}
__device__ __forceinline__ void ldm4(uint32_t* r, uint32_t addr) {
    asm volatile("ldmatrix.sync.aligned.m8n8.x4.shared.b16 {%0,%1,%2,%3}, [%4];"
        : "=r"(r[0]), "=r"(r[1]), "=r"(r[2]), "=r"(r[3]) : "r"(addr));
}
__device__ __forceinline__ void mma8(float* d, const uint32_t* a, uint32_t b0, uint32_t b1) {
    asm volatile("mma.sync.aligned.m16n8k8.row.col.f32.tf32.tf32.f32 "
        "{%0,%1,%2,%3}, {%4,%5,%6,%7}, {%8,%9}, {%0,%1,%2,%3};"
        : "+f"(d[0]), "+f"(d[1]), "+f"(d[2]), "+f"(d[3])
        : "r"(a[0]), "r"(a[1]), "r"(a[2]), "r"(a[3]), "r"(b0), "r"(b1));
}
__device__ __forceinline__ uint32_t smem_u32(const void* p) {
    return (uint32_t)__cvta_generic_to_shared(p);
}

// Swizzled byte offset inside a [rows][64]-float region: row stride 256B,
// 16B-unit column XOR'ed with (row&7) -> conflict-free ldmatrix phases.
__device__ __forceinline__ int swzo(int regionFloat, int row, int col) {
    return regionFloat*4 + row*256 + ((((col>>2) ^ (row&7)))<<4) + ((col&3)<<2);
}

// smem regions (float offsets)
#define R_QHI 0        // [128][64]
#define R_QLO 8192     // [128][64]
#define R_KHI 16384    // [64][64]  (aliased: P [128][64], O-staging [64][128])
#define R_KLO 20480    // [64][64]
#define R_VS  24576    // [64][64]  rows = channel, cols = key
#define R_EA  28672    // [64]
#define SMEM_FLOATS (28672 + 64)   // 114,944 bytes

// ---------------------------------------------------------------------------
// P1: maxpool(x), maxpool(c2), k = Wq*xp + bq, v = xp, edge gate ea
// ---------------------------------------------------------------------------
__global__ void __launch_bounds__(256) prep_kernel(
    const float* __restrict__ c2, const float* __restrict__ x,
    const float* __restrict__ w_ea1, const float* __restrict__ bn_w,
    const float* __restrict__ bn_b,  const float* __restrict__ bn_m,
    const float* __restrict__ bn_v,  const float* __restrict__ w_ea2,
    const float* __restrict__ b_ea2, const float* __restrict__ w_q,
    const float* __restrict__ b_q)
{
    extern __shared__ float sm[];
    float* sWq  = sm;                 // [64][65]
    float* sW1  = sWq  + 64*65;       // [64][129]
    float* sXp  = sW1  + 64*129;      // [32][65]
    float* sC2p = sXp  + 32*65;       // [32][65]
    float* sH   = sC2p + 32*65;       // [32][65]

    const int b   = blockIdx.y;
    const int m0  = blockIdx.x * 32;
    const int tid = threadIdx.x;

    for (int i = tid; i < 64*64;  i += 256) sWq[(i>>6)*65  + (i&63)]  = w_q[i];
    for (int i = tid; i < 64*128; i += 256) sW1[(i>>7)*129 + (i&127)] = w_ea1[i];

    for (int job = tid; job < 2048; job += 256) {
        int c = job >> 5, p = job & 31;
        int m = m0 + p;
        int py = m / WP, px = m % WP;
        int base = ((b*CC + c)*HH + 2*py)*WW + 2*px;
        float vx = fmaxf(fmaxf(x[base],  x[base+1]),  fmaxf(x[base+WW],  x[base+WW+1]));
        float vc = fmaxf(fmaxf(c2[base], c2[base+1]), fmaxf(c2[base+WW], c2[base+WW+1]));
        sXp [p*65 + c] = vx;
        sC2p[p*65 + c] = vc;
        g_v[(b*CC + c)*MM + m] = vx;
    }
    __syncthreads();

    for (int job = tid; job < 2048; job += 256) {
        int o = job >> 5, p = job & 31;
        const float* wr = sWq + o*65;
        const float* xr = sXp + p*65;
        const float* cr = sC2p + p*65;
        float acc = b_q[o];
        #pragma unroll 16
        for (int c = 0; c < 64; c++) acc += wr[c]*xr[c];
        g_k[(b*KK + o)*MM + m0 + p] = acc;

        const float* w1 = sW1 + o*129;
        float h = 0.f;
        #pragma unroll 16
        for (int c = 0; c < 64; c++) h += w1[c]*cr[c];
        #pragma unroll 16
        for (int c = 0; c < 64; c++) h += w1[64+c]*xr[c];
        float scale = bn_w[o] * rsqrtf(bn_v[o] + 1e-5f);
        h = (h - bn_m[o]) * scale + bn_b[o];
        sH[p*65 + o] = fmaxf(h, 0.f);
    }
    __syncthreads();

    if (tid < 32) {
        int p = tid;
        const float* hr = sH + p*65;
        float acc = b_ea2[0];
        #pragma unroll 16
        for (int o = 0; o < 64; o++) acc += w_ea2[o]*hr[o];
        g_ea[b*MM + m0 + p] = 1.f / (1.f + __expf(-acc));
    }
}

// ---------------------------------------------------------------------------
// P2: q = Wq * x + bq at full resolution
// ---------------------------------------------------------------------------
__global__ void __launch_bounds__(256) q_kernel(
    const float* __restrict__ x, const float* __restrict__ w_q,
    const float* __restrict__ b_q)
{
    __shared__ float sX [64*65];
    __shared__ float sWq[64*65];
    const int b   = blockIdx.y;
    const int n0  = blockIdx.x * 64;
    const int tid = threadIdx.x;

    for (int i = tid; i < 64*64; i += 256) sWq[(i>>6)*65 + (i&63)] = w_q[i];
    for (int i = tid; i < 64*64; i += 256) {
        int c = i >> 6, p = i & 63;
        sX[p*65 + c] = x[(b*CC + c)*NN + n0 + p];
    }
    __syncthreads();
    for (int job = tid; job < 4096; job += 256) {
        int o = job >> 6, p = job & 63;
        const float* wr = sWq + o*65;
        const float* xr = sX  + p*65;
        float acc = b_q[o];
        #pragma unroll 16
        for (int c = 0; c < 64; c++) acc += wr[c]*xr[c];
        g_q[(b*KK + o)*NN + n0 + p] = acc;
    }
}

// ---------------------------------------------------------------------------
// A: flash attention with tf32 mma.sync.
// Block = 128 query rows, 8 warps x 16 rows, key tiles of 64.
// QK: split-tf32 (hi*hi + hi*lo + lo*hi). PV: single tf32.
// ---------------------------------------------------------------------------
__global__ void __launch_bounds__(256) attn_kernel(
    const float* __restrict__ x, const float* __restrict__ gamma,
    float* __restrict__ out)
{
    extern __shared__ float sm[];
    const uint32_t sb = smem_u32(sm);
    char* smc = (char*)sm;

    const int b    = blockIdx.y;
    const int n0   = blockIdx.x * 128;
    const int tid  = threadIdx.x;
    const int lane = tid & 31;
    const int warp = tid >> 5;
    const int rbase = warp * 16;

    // lane constants for ldmatrix addressing
    const int arow = rbase + (lane & 7) + (lane & 8);   // A-frag row (Q / P)
    const int aub  = (lane >> 4) & 1;                   // A unit offset
    const int brow = (lane & 7) + ((lane & 16) ? 8 : 0);// B-frag row offset (K / V)
    const int bub  = (lane >> 3) & 1;                   // B unit offset
    const int gid  = lane >> 2;                         // frag row-in-16
    const int colb = 2 * (lane & 3);                    // frag col pair base
    const int prow0 = rbase + gid;

    const float g = gamma[0];

    // ---- load Q block, split into tf32 hi/lo -------------------------------
    for (int i = tid; i < 8192; i += 256) {
        int d = i >> 7, r = i & 127;
        float q = g_q[(b*KK + d)*NN + n0 + r];
        float hif = tf32f(q);
        float lof = tf32f(q - hif);
        *(float*)(smc + swzo(R_QHI, r, d)) = hif;
        *(float*)(smc + swzo(R_QLO, r, d)) = lof;
    }

    float m0 = -1e30f, m1 = -1e30f, l0 = 0.f, l1 = 0.f;
    float O[8][4];
    #pragma unroll
    for (int nc = 0; nc < 8; nc++)
        #pragma unroll
        for (int j = 0; j < 4; j++) O[nc][j] = 0.f;

    for (int t = 0; t < MM/64; t++) {
        const int mb = t * 64;
        __syncthreads();   // previous tile's PV reads done
        // ---- load K tile (hi/lo) and V tile (tf32) ------------------------
        for (int i = tid; i < 4096; i += 256) {
            int d = i >> 6, j = i & 63;
            float k = g_k[(b*KK + d)*MM + mb + j];
            float hif = tf32f(k);
            float lof = tf32f(k - hif);
            *(float*)(smc + swzo(R_KHI, j, d)) = hif;
            *(float*)(smc + swzo(R_KLO, j, d)) = lof;
            float v = g_v[(b*CC + d)*MM + mb + j];
            *(float*)(smc + swzo(R_VS, d, j)) = tf32f(v);
        }
        if (tid < 64) sm[R_EA + tid] = g_ea[b*MM + mb + tid];
        __syncthreads();

        // ---- S = Q K^T (split-tf32, 3 MMAs) -------------------------------
        float S[8][4];
        #pragma unroll
        for (int nc = 0; nc < 8; nc++)
            #pragma unroll
            for (int j = 0; j < 4; j++) S[nc][j] = 0.f;

        #pragma unroll
        for (int kc = 0; kc < 8; kc++) {
            uint32_t ah[4], al[4];
            int au = (kc*2 + aub) ^ (arow & 7);
            ldm4(ah, sb + R_QHI*4 + arow*256 + (au<<4));
            ldm4(al, sb + R_QLO*4 + arow*256 + (au<<4));
            #pragma unroll
            for (int nc2 = 0; nc2 < 4; nc2++) {
                int key = nc2*16 + brow;
                int bo  = key*256 + (((kc*2 + bub) ^ (key & 7))<<4);
                uint32_t bh[4], bl[4];
                ldm4(bh, sb + R_KHI*4 + bo);
                ldm4(bl, sb + R_KLO*4 + bo);
                mma8(S[nc2*2],   ah, bh[0], bh[1]);
                mma8(S[nc2*2+1], ah, bh[2], bh[3]);
                mma8(S[nc2*2],   ah, bl[0], bl[1]);
                mma8(S[nc2*2+1], ah, bl[2], bl[3]);
                mma8(S[nc2*2],   al, bh[0], bh[1]);
                mma8(S[nc2*2+1], al, bh[2], bh[3]);
            }
        }

        // ---- edge gate ----------------------------------------------------
        #pragma unroll
        for (int nc = 0; nc < 8; nc++) {
            float2 e = *(float2*)&sm[R_EA + nc*8 + colb];
            S[nc][0] *= e.x; S[nc][1] *= e.y;
            S[nc][2] *= e.x; S[nc][3] *= e.y;
        }

        // ---- online softmax (rows prow0, prow0+8) -------------------------
        float rm0 = -1e30f, rm1 = -1e30f;
        #pragma unroll
        for (int nc = 0; nc < 8; nc++) {
            rm0 = fmaxf(rm0, fmaxf(S[nc][0], S[nc][1]));
            rm1 = fmaxf(rm1, fmaxf(S[nc][2], S[nc][3]));
        }
        rm0 = fmaxf(rm0, __shfl_xor_sync(0xffffffffu, rm0, 1));
        rm0 = fmaxf(rm0, __shfl_xor_sync(0xffffffffu, rm0, 2));
        rm1 = fmaxf(rm1, __shfl_xor_sync(0xffffffffu, rm1, 1));
        rm1 = fmaxf(rm1, __shfl_xor_sync(0xffffffffu, rm1, 2));
        float mn0 = fmaxf(m0, rm0), mn1 = fmaxf(m1, rm1);
        float a0 = __expf(m0 - mn0), a1 = __expf(m1 - mn1);
        m0 = mn0; m1 = mn1;
        float s0 = 0.f, s1 = 0.f;
        #pragma unroll
        for (int nc = 0; nc < 8; nc++) {
            S[nc][0] = __expf(S[nc][0] - mn0); s0 += S[nc][0];
            S[nc][1] = __expf(S[nc][1] - mn0); s0 += S[nc][1];
            S[nc][2] = __expf(S[nc][2] - mn1); s1 += S[nc][2];
            S[nc][3] = __expf(S[nc][3] - mn1); s1 += S[nc][3];
        }
        s0 += __shfl_xor_sync(0xffffffffu, s0, 1);
        s0 += __shfl_xor_sync(0xffffffffu, s0, 2);
        s1 += __shfl_xor_sync(0xffffffffu, s1, 1);
        s1 += __shfl_xor_sync(0xffffffffu, s1, 2);
        l0 = l0*a0 + s0;
        l1 = l1*a1 + s1;
        #pragma unroll
        for (int nc = 0; nc < 8; nc++) {
            O[nc][0] *= a0; O[nc][1] *= a0;
            O[nc][2] *= a1; O[nc][3] *= a1;
        }

        // ---- P -> smem (alias K region; tf32-rounded) ---------------------
        __syncthreads();   // all warps done reading K
        #pragma unroll
        for (int nc = 0; nc < 8; nc++) {
            int col = nc*8 + colb;
            float2 p0 = { tf32f(S[nc][0]), tf32f(S[nc][1]) };
            float2 p1 = { tf32f(S[nc][2]), tf32f(S[nc][3]) };
            *(float2*)(smc + swzo(R_KHI, prow0,     col)) = p0;
            *(float2*)(smc + swzo(R_KHI, prow0 + 8, col)) = p1;
        }
        __syncthreads();

        // ---- O += P V^T ---------------------------------------------------
        #pragma unroll
        for (int kc = 0; kc < 8; kc++) {
            uint32_t ap[4];
            int au = (kc*2 + aub) ^ (arow & 7);
            ldm4(ap, sb + R_KHI*4 + arow*256 + (au<<4));
            #pragma unroll
            for (int nc2 = 0; nc2 < 4; nc2++) {
                int ch = nc2*16 + brow;
                int bo = ch*256 + (((kc*2 + bub) ^ (ch & 7))<<4);
                uint32_t bv[4];
                ldm4(bv, sb + R_VS*4 + bo);
                mma8(O[nc2*2],   ap, bv[0], bv[1]);
                mma8(O[nc2*2+1], ap, bv[2], bv[3]);
            }
        }
    }

    // ---- finalize ---------------------------------------------------------
    float inv0 = 1.f / l0, inv1 = 1.f / l1;
    #pragma unroll
    for (int nc = 0; nc < 8; nc++) {
        O[nc][0] *= inv0; O[nc][1] *= inv0;
        O[nc][2] *= inv1; O[nc][3] *= inv1;
    }

    __syncthreads();
    // stage O to smem as [ch][row] (stride 128) in the K region
    float* Ost = sm + R_KHI;
    #pragma unroll
    for (int nc = 0; nc < 8; nc++) {
        int c0 = nc*8 + colb;
        Ost[(c0    )*128 + prow0    ] = O[nc][0];
        Ost[(c0 + 1)*128 + prow0    ] = O[nc][1];
        Ost[(c0    )*128 + prow0 + 8] = O[nc][2];
        Ost[(c0 + 1)*128 + prow0 + 8] = O[nc][3];
    }
    __syncthreads();
    for (int i = tid; i < 8192; i += 256) {
        int c = i >> 7, r = i & 127;
        int gi = (b*CC + c)*NN + n0 + r;
        out[gi] = g * Ost[c*128 + r] + x[gi];
    }
}

// ---------------------------------------------------------------------------
extern "C" void kernel_launch(void* const* d_in, const int* in_sizes, int n_in,
                              void* d_out, int out_size)
{
    const float* c2    = (const float*)d_in[0];
    const float* x     = (const float*)d_in[1];
    const float* w_ea1 = (const float*)d_in[2];
    const float* bn_w  = (const float*)d_in[3];
    const float* bn_b  = (const float*)d_in[4];
    const float* bn_m  = (const float*)d_in[5];
    const float* bn_v  = (const float*)d_in[6];
    const float* w_ea2 = (const float*)d_in[7];
    const float* b_ea2 = (const float*)d_in[8];
    const float* w_q   = (const float*)d_in[9];
    const float* b_q   = (const float*)d_in[10];
    const float* gamma = (const float*)d_in[11];
    float* out = (float*)d_out;

    const int P1_SMEM   = (64*65 + 64*129 + 3*32*65) * (int)sizeof(float);   // 74624 B
    const int ATTN_SMEM = SMEM_FLOATS * (int)sizeof(float);                  // 114944 B

    cudaFuncSetAttribute(prep_kernel, cudaFuncAttributeMaxDynamicSharedMemorySize, P1_SMEM);
    cudaFuncSetAttribute(attn_kernel, cudaFuncAttributeMaxDynamicSharedMemorySize, ATTN_SMEM);

    prep_kernel<<<dim3(MM/32, BB), 256, P1_SMEM>>>(c2, x, w_ea1, bn_w, bn_b, bn_m,
                                                   bn_v, w_ea2, b_ea2, w_q, b_q);
    q_kernel<<<dim3(NN/64, BB), 256>>>(x, w_q, b_q);
    attn_kernel<<<dim3(NN/128, BB), 256, ATTN_SMEM>>>(x, gamma, out);
}

// round 5
// speedup vs baseline: 2.7286x; 1.3200x over previous
#include <cuda_runtime.h>
#include <cuda_bf16.h>
#include <math.h>
#include <stdint.h>

#define BB 4
#define CC 64
#define HH 96
#define WW 96
#define NN (HH*WW)      // 9216
#define HP (HH/2)
#define WP (WW/2)
#define MM (HP*WP)      // 2304
#define KK 64

// Scratch (no allocations allowed)
__device__ float g_q [BB*KK*NN];   // q, [b][k][n]
__device__ float g_k [BB*KK*MM];   // k, [b][k][m]
__device__ float g_v [BB*CC*MM];   // pooled x, [b][c][m]
__device__ float g_ea[BB*MM];      // sigmoid edge gate, [b][m]

// ---- mma helpers ----------------------------------------------------------
__device__ __forceinline__ void ldm4(uint32_t* r, uint32_t addr) {
    asm volatile("ldmatrix.sync.aligned.m8n8.x4.shared.b16 {%0,%1,%2,%3}, [%4];"
        : "=r"(r[0]), "=r"(r[1]), "=r"(r[2]), "=r"(r[3]) : "r"(addr));
}
__device__ __forceinline__ void mma16(float* d, const uint32_t* a, uint32_t b0, uint32_t b1) {
    asm volatile("mma.sync.aligned.m16n8k16.row.col.f32.bf16.bf16.f32 "
        "{%0,%1,%2,%3}, {%4,%5,%6,%7}, {%8,%9}, {%0,%1,%2,%3};"
        : "+f"(d[0]), "+f"(d[1]), "+f"(d[2]), "+f"(d[3])
        : "r"(a[0]), "r"(a[1]), "r"(a[2]), "r"(a[3]), "r"(b0), "r"(b1));
}
__device__ __forceinline__ uint32_t smem_u32(const void* p) {
    return (uint32_t)__cvta_generic_to_shared(p);
}
// pack (lo,hi) floats -> bf16x2 (elem0 = lo)
__device__ __forceinline__ uint32_t pack_bf2(float lo, float hi) {
    uint32_t r; asm("cvt.rn.bf16x2.f32 %0, %1, %2;" : "=r"(r) : "f"(hi), "f"(lo)); return r;
}

// smem regions (BYTE offsets). All matrix regions use 128B rows with the
// 16B-unit XOR(row&7) swizzle -> conflict-free ldmatrix.
#define B_QHI 0        // [128 r][64 d] bf16
#define B_QLO 16384
#define B_KHI 32768    // [64 key][64 d] bf16
#define B_KLO 40960
#define B_VS  49152    // [64 ch][64 key] bf16
#define B_PHI 57344    // [128 r][64 key] bf16 (per-warp private rows)
#define B_PLO 73728
#define B_EA  90112    // [64] float
#define ATTN_SMEM_BYTES 90368

// ---------------------------------------------------------------------------
// P1: maxpool(x), maxpool(c2), k = Wq*xp + bq, v = xp, edge gate ea
// ---------------------------------------------------------------------------
__global__ void __launch_bounds__(256) prep_kernel(
    const float* __restrict__ c2, const float* __restrict__ x,
    const float* __restrict__ w_ea1, const float* __restrict__ bn_w,
    const float* __restrict__ bn_b,  const float* __restrict__ bn_m,
    const float* __restrict__ bn_v,  const float* __restrict__ w_ea2,
    const float* __restrict__ b_ea2, const float* __restrict__ w_q,
    const float* __restrict__ b_q)
{
    extern __shared__ float sm[];
    float* sWq  = sm;                 // [64][65]
    float* sW1  = sWq  + 64*65;       // [64][129]
    float* sXp  = sW1  + 64*129;      // [32][65]
    float* sC2p = sXp  + 32*65;       // [32][65]
    float* sH   = sC2p + 32*65;       // [32][65]

    const int b   = blockIdx.y;
    const int m0  = blockIdx.x * 32;
    const int tid = threadIdx.x;

    for (int i = tid; i < 64*64;  i += 256) sWq[(i>>6)*65  + (i&63)]  = w_q[i];
    for (int i = tid; i < 64*128; i += 256) sW1[(i>>7)*129 + (i&127)] = w_ea1[i];

    for (int job = tid; job < 2048; job += 256) {
        int c = job >> 5, p = job & 31;
        int m = m0 + p;
        int py = m / WP, px = m % WP;
        int base = ((b*CC + c)*HH + 2*py)*WW + 2*px;
        float vx = fmaxf(fmaxf(x[base],  x[base+1]),  fmaxf(x[base+WW],  x[base+WW+1]));
        float vc = fmaxf(fmaxf(c2[base], c2[base+1]), fmaxf(c2[base+WW], c2[base+WW+1]));
        sXp [p*65 + c] = vx;
        sC2p[p*65 + c] = vc;
        g_v[(b*CC + c)*MM + m] = vx;
    }
    __syncthreads();

    // 4 outputs per job -> 4-way ILP on the FMA chains
    for (int job = tid; job < 512; job += 256) {
        int og = (job >> 5) << 2;
        int p  = job & 31;
        const float* xr = sXp  + p*65;
        const float* cr = sC2p + p*65;
        const float *w0 = sWq + og*65, *w1 = w0+65, *w2 = w0+130, *w3 = w0+195;
        float a0 = b_q[og], a1 = b_q[og+1], a2 = b_q[og+2], a3 = b_q[og+3];
        #pragma unroll 8
        for (int c = 0; c < 64; c++) {
            float xv = xr[c];
            a0 += w0[c]*xv; a1 += w1[c]*xv; a2 += w2[c]*xv; a3 += w3[c]*xv;
        }
        g_k[(b*KK+og  )*MM + m0 + p] = a0;
        g_k[(b*KK+og+1)*MM + m0 + p] = a1;
        g_k[(b*KK+og+2)*MM + m0 + p] = a2;
        g_k[(b*KK+og+3)*MM + m0 + p] = a3;

        const float *u0 = sW1 + og*129, *u1 = u0+129, *u2 = u0+258, *u3 = u0+387;
        float h0=0.f, h1=0.f, h2=0.f, h3=0.f;
        #pragma unroll 8
        for (int c = 0; c < 64; c++) {
            float cv = cr[c];
            h0 += u0[c]*cv; h1 += u1[c]*cv; h2 += u2[c]*cv; h3 += u3[c]*cv;
        }
        #pragma unroll 8
        for (int c = 0; c < 64; c++) {
            float xv = xr[c];
            h0 += u0[64+c]*xv; h1 += u1[64+c]*xv; h2 += u2[64+c]*xv; h3 += u3[64+c]*xv;
        }
        float hh[4] = {h0, h1, h2, h3};
        #pragma unroll
        for (int k2 = 0; k2 < 4; k2++) {
            int o = og + k2;
            float scale = bn_w[o] * rsqrtf(bn_v[o] + 1e-5f);
            float hv = (hh[k2] - bn_m[o]) * scale + bn_b[o];
            sH[p*65 + o] = fmaxf(hv, 0.f);
        }
    }
    __syncthreads();

    if (tid < 32) {
        int p = tid;
        const float* hr = sH + p*65;
        float acc = b_ea2[0];
        #pragma unroll 16
        for (int o = 0; o < 64; o++) acc += w_ea2[o]*hr[o];
        g_ea[b*MM + m0 + p] = 1.f / (1.f + __expf(-acc));
    }
}

// ---------------------------------------------------------------------------
// P2: q = Wq * x + bq at full resolution (4-way ILP)
// ---------------------------------------------------------------------------
__global__ void __launch_bounds__(256) q_kernel(
    const float* __restrict__ x, const float* __restrict__ w_q,
    const float* __restrict__ b_q)
{
    __shared__ float sX [64*65];
    __shared__ float sWq[64*65];
    const int b   = blockIdx.y;
    const int n0  = blockIdx.x * 64;
    const int tid = threadIdx.x;

    for (int i = tid; i < 64*64; i += 256) sWq[(i>>6)*65 + (i&63)] = w_q[i];
    for (int i = tid; i < 64*64; i += 256) {
        int c = i >> 6, p = i & 63;
        sX[p*65 + c] = x[(b*CC + c)*NN + n0 + p];
    }
    __syncthreads();
    for (int job = tid; job < 1024; job += 256) {
        int og = (job >> 6) << 2;
        int p  = job & 63;
        const float* xr = sX + p*65;
        const float *w0 = sWq + og*65, *w1 = w0+65, *w2 = w0+130, *w3 = w0+195;
        float a0 = b_q[og], a1 = b_q[og+1], a2 = b_q[og+2], a3 = b_q[og+3];
        #pragma unroll 8
        for (int c = 0; c < 64; c++) {
            float xv = xr[c];
            a0 += w0[c]*xv; a1 += w1[c]*xv; a2 += w2[c]*xv; a3 += w3[c]*xv;
        }
        g_q[(b*KK+og  )*NN + n0 + p] = a0;
        g_q[(b*KK+og+1)*NN + n0 + p] = a1;
        g_q[(b*KK+og+2)*NN + n0 + p] = a2;
        g_q[(b*KK+og+3)*NN + n0 + p] = a3;
    }
}

// ---------------------------------------------------------------------------
// A: flash attention, bf16 m16n8k16 mma.
// QK: 3-term bf16 split. PV: P split hi/lo, V single bf16.
// Block = 128 query rows, 8 warps x 16 rows, key tiles of 64.
// ---------------------------------------------------------------------------
__global__ void __launch_bounds__(256) attn_kernel(
    const float* __restrict__ x, const float* __restrict__ gamma,
    float* __restrict__ out)
{
    extern __shared__ float sm[];
    const uint32_t sb = smem_u32(sm);
    char* smc = (char*)sm;

    const int b    = blockIdx.y;
    const int n0   = blockIdx.x * 128;
    const int tid  = threadIdx.x;
    const int lane = tid & 31;
    const int warp = tid >> 5;
    const int rbase = warp * 16;

    const int lrow  = lane & 15;        // ldmatrix row-in-16
    const int khalf = lane >> 4;        // ldmatrix k-half unit
    const int gid   = lane >> 2;
    const int colb  = 2 * (lane & 3);
    const int prow0 = rbase + gid;
    const int arow  = rbase + lrow;     // A-frag row (Q / P)

    const float g = gamma[0];

    // ---- load Q block, split to bf16 hi/lo --------------------------------
    for (int i = tid; i < 8192; i += 256) {
        int d = i >> 7, r = i & 127;
        float q = g_q[(b*KK + d)*NN + n0 + r];
        __nv_bfloat16 hi = __float2bfloat16(q);
        __nv_bfloat16 lo = __float2bfloat16(q - __bfloat162float(hi));
        int off = r*128 + ((((d>>3) ^ (r&7)))<<4) + (d&7)*2;
        *(__nv_bfloat16*)(smc + B_QHI + off) = hi;
        *(__nv_bfloat16*)(smc + B_QLO + off) = lo;
    }

    float m0 = -1e30f, m1 = -1e30f, l0 = 0.f, l1 = 0.f;
    float O[8][4];
    #pragma unroll
    for (int nc = 0; nc < 8; nc++)
        #pragma unroll
        for (int j = 0; j < 4; j++) O[nc][j] = 0.f;

    for (int t = 0; t < MM/64; t++) {
        const int mb = t * 64;
        __syncthreads();   // previous tile's K/V reads done
        for (int i = tid; i < 4096; i += 256) {
            int d = i >> 6, j = i & 63;
            float k = g_k[(b*KK + d)*MM + mb + j];
            __nv_bfloat16 hi = __float2bfloat16(k);
            __nv_bfloat16 lo = __float2bfloat16(k - __bfloat162float(hi));
            int koff = j*128 + ((((d>>3) ^ (j&7)))<<4) + (d&7)*2;
            *(__nv_bfloat16*)(smc + B_KHI + koff) = hi;
            *(__nv_bfloat16*)(smc + B_KLO + koff) = lo;
            float v = g_v[(b*CC + d)*MM + mb + j];   // d = channel here
            int voff = d*128 + ((((j>>3) ^ (d&7)))<<4) + (j&7)*2;
            *(__nv_bfloat16*)(smc + B_VS + voff) = __float2bfloat16(v);
        }
        if (tid < 64) *(float*)(smc + B_EA + tid*4) = g_ea[b*MM + mb + tid];
        __syncthreads();

        // ---- S = Q K^T (3-term bf16 split) --------------------------------
        float S[8][4];
        #pragma unroll
        for (int nc = 0; nc < 8; nc++)
            #pragma unroll
            for (int j = 0; j < 4; j++) S[nc][j] = 0.f;

        #pragma unroll
        for (int kc = 0; kc < 4; kc++) {
            const int unit = kc*2 + khalf;
            uint32_t ah[4], al[4];
            uint32_t aoff = arow*128 + (((unit ^ (arow&7)))<<4);
            ldm4(ah, sb + B_QHI + aoff);
            ldm4(al, sb + B_QLO + aoff);
            #pragma unroll
            for (int nc2 = 0; nc2 < 4; nc2++) {
                int key = nc2*16 + lrow;
                uint32_t boff = key*128 + (((unit ^ (key&7)))<<4);
                uint32_t bh[4], bl[4];
                ldm4(bh, sb + B_KHI + boff);
                ldm4(bl, sb + B_KLO + boff);
                mma16(S[nc2*2],   ah, bh[0], bh[2]);
                mma16(S[nc2*2+1], ah, bh[1], bh[3]);
                mma16(S[nc2*2],   ah, bl[0], bl[2]);
                mma16(S[nc2*2+1], ah, bl[1], bl[3]);
                mma16(S[nc2*2],   al, bh[0], bh[2]);
                mma16(S[nc2*2+1], al, bh[1], bh[3]);
            }
        }

        // ---- edge gate ----------------------------------------------------
        #pragma unroll
        for (int nc = 0; nc < 8; nc++) {
            float2 e = *(float2*)(smc + B_EA + (nc*8 + colb)*4);
            S[nc][0] *= e.x; S[nc][1] *= e.y;
            S[nc][2] *= e.x; S[nc][3] *= e.y;
        }

        // ---- online softmax ----------------------------------------------
        float rm0 = -1e30f, rm1 = -1e30f;
        #pragma unroll
        for (int nc = 0; nc < 8; nc++) {
            rm0 = fmaxf(rm0, fmaxf(S[nc][0], S[nc][1]));
            rm1 = fmaxf(rm1, fmaxf(S[nc][2], S[nc][3]));
        }
        rm0 = fmaxf(rm0, __shfl_xor_sync(0xffffffffu, rm0, 1));
        rm0 = fmaxf(rm0, __shfl_xor_sync(0xffffffffu, rm0, 2));
        rm1 = fmaxf(rm1, __shfl_xor_sync(0xffffffffu, rm1, 1));
        rm1 = fmaxf(rm1, __shfl_xor_sync(0xffffffffu, rm1, 2));
        float mn0 = fmaxf(m0, rm0), mn1 = fmaxf(m1, rm1);
        float a0 = __expf(m0 - mn0), a1 = __expf(m1 - mn1);
        m0 = mn0; m1 = mn1;
        float s0 = 0.f, s1 = 0.f;
        #pragma unroll
        for (int nc = 0; nc < 8; nc++) {
            S[nc][0] = __expf(S[nc][0] - mn0); s0 += S[nc][0];
            S[nc][1] = __expf(S[nc][1] - mn0); s0 += S[nc][1];
            S[nc][2] = __expf(S[nc][2] - mn1); s1 += S[nc][2];
            S[nc][3] = __expf(S[nc][3] - mn1); s1 += S[nc][3];
        }
        s0 += __shfl_xor_sync(0xffffffffu, s0, 1);
        s0 += __shfl_xor_sync(0xffffffffu, s0, 2);
        s1 += __shfl_xor_sync(0xffffffffu, s1, 1);
        s1 += __shfl_xor_sync(0xffffffffu, s1, 2);
        l0 = l0*a0 + s0;
        l1 = l1*a1 + s1;
        #pragma unroll
        for (int nc = 0; nc < 8; nc++) {
            O[nc][0] *= a0; O[nc][1] *= a0;
            O[nc][2] *= a1; O[nc][3] *= a1;
        }

        // ---- P -> smem bf16 hi/lo (per-warp-private rows: no block sync) --
        #pragma unroll
        for (int nc = 0; nc < 8; nc++) {
            // row prow0: keys (nc*8+colb, +1)
            uint32_t hi2 = pack_bf2(S[nc][0], S[nc][1]);
            __nv_bfloat162 h2 = *reinterpret_cast<__nv_bfloat162*>(&hi2);
            uint32_t lo2 = pack_bf2(S[nc][0] - __bfloat162float(h2.x),
                                    S[nc][1] - __bfloat162float(h2.y));
            int off0 = prow0*128 + (((nc ^ (prow0&7)))<<4) + (lane&3)*4;
            *(uint32_t*)(smc + B_PHI + off0) = hi2;
            *(uint32_t*)(smc + B_PLO + off0) = lo2;
            // row prow0+8
            uint32_t hi2b = pack_bf2(S[nc][2], S[nc][3]);
            __nv_bfloat162 h2b = *reinterpret_cast<__nv_bfloat162*>(&hi2b);
            uint32_t lo2b = pack_bf2(S[nc][2] - __bfloat162float(h2b.x),
                                     S[nc][3] - __bfloat162float(h2b.y));
            int off1 = (prow0+8)*128 + (((nc ^ ((prow0+8)&7)))<<4) + (lane&3)*4;
            *(uint32_t*)(smc + B_PHI + off1) = hi2b;
            *(uint32_t*)(smc + B_PLO + off1) = lo2b;
        }
        __syncwarp();

        // ---- O += P V^T (P split, V single) -------------------------------
        #pragma unroll
        for (int kc = 0; kc < 4; kc++) {
            const int unit = kc*2 + khalf;
            uint32_t ph[4], pl[4];
            uint32_t aoff = arow*128 + (((unit ^ (arow&7)))<<4);
            ldm4(ph, sb + B_PHI + aoff);
            ldm4(pl, sb + B_PLO + aoff);
            #pragma unroll
            for (int nc2 = 0; nc2 < 4; nc2++) {
                int ch = nc2*16 + lrow;
                uint32_t boff = ch*128 + (((unit ^ (ch&7)))<<4);
                uint32_t bv[4];
                ldm4(bv, sb + B_VS + boff);
                mma16(O[nc2*2],   ph, bv[0], bv[2]);
                mma16(O[nc2*2+1], ph, bv[1], bv[3]);
                mma16(O[nc2*2],   pl, bv[0], bv[2]);
                mma16(O[nc2*2+1], pl, bv[1], bv[3]);
            }
        }
    }

    // ---- finalize ---------------------------------------------------------
    float inv0 = 1.f / l0, inv1 = 1.f / l1;
    #pragma unroll
    for (int nc = 0; nc < 8; nc++) {
        O[nc][0] *= inv0; O[nc][1] *= inv0;
        O[nc][2] *= inv1; O[nc][3] *= inv1;
    }

    __syncthreads();   // everyone done with Q region
    float* Ost = sm;   // [64 ch][128 row] fp32, aliases Q region (32 KB)
    #pragma unroll
    for (int nc = 0; nc < 8; nc++) {
        int c0 = nc*8 + colb;
        Ost[(c0    )*128 + prow0    ] = O[nc][0];
        Ost[(c0 + 1)*128 + prow0    ] = O[nc][1];
        Ost[(c0    )*128 + prow0 + 8] = O[nc][2];
        Ost[(c0 + 1)*128 + prow0 + 8] = O[nc][3];
    }
    __syncthreads();
    for (int i = tid; i < 8192; i += 256) {
        int c = i >> 7, r = i & 127;
        int gi = (b*CC + c)*NN + n0 + r;
        out[gi] = g * Ost[c*128 + r] + x[gi];
    }
}

// ---------------------------------------------------------------------------
extern "C" void kernel_launch(void* const* d_in, const int* in_sizes, int n_in,
                              void* d_out, int out_size)
{
    const float* c2    = (const float*)d_in[0];
    const float* x     = (const float*)d_in[1];
    const float* w_ea1 = (const float*)d_in[2];
    const float* bn_w  = (const float*)d_in[3];
    const float* bn_b  = (const float*)d_in[4];
    const float* bn_m  = (const float*)d_in[5];
    const float* bn_v  = (const float*)d_in[6];
    const float* w_ea2 = (const float*)d_in[7];
    const float* b_ea2 = (const float*)d_in[8];
    const float* w_q   = (const float*)d_in[9];
    const float* b_q   = (const float*)d_in[10];
    const float* gamma = (const float*)d_in[11];
    float* out = (float*)d_out;

    const int P1_SMEM = (64*65 + 64*129 + 3*32*65) * (int)sizeof(float);   // 74624 B

    cudaFuncSetAttribute(prep_kernel, cudaFuncAttributeMaxDynamicSharedMemorySize, P1_SMEM);
    cudaFuncSetAttribute(attn_kernel, cudaFuncAttributeMaxDynamicSharedMemorySize, ATTN_SMEM_BYTES);

    prep_kernel<<<dim3(MM/32, BB), 256, P1_SMEM>>>(c2, x, w_ea1, bn_w, bn_b, bn_m,
                                                   bn_v, w_ea2, b_ea2, w_q, b_q);
    q_kernel<<<dim3(NN/64, BB), 256>>>(x, w_q, b_q);
    attn_kernel<<<dim3(NN/128, BB), 256, ATTN_SMEM_BYTES>>>(x, gamma, out);
}